// round 8
// baseline (speedup 1.0000x reference)
#include <cuda_runtime.h>

#define NROW 512
#define DDIM 768
#define TS   16      // pair-tile side (i x j per block)
#define DC   192     // d-chunk per smem stage
#define DCPAD 196    // padded float stride (196 = 49 float4 -> conflict-free 2-phase LDS.128)

__device__ float g_h1[NROW * DDIM];   // 0.5 * softmax(z1)
__device__ float g_h2[NROW * DDIM];   // 0.5 * softmax(z2)
__device__ float g_A[NROW];           // sum_d p1*log(p1+eps) per row (natural log)
__device__ float g_B[NROW];
__device__ float g_tileSum[1024];     // per 16x16 tile: sum_{ij in tile} C_ij
__device__ float g_tileDiag[1024];    // per tile: sum over diagonal (i==j) C_ij

__constant__ float c_eps = 1e-8f;

// ---------------------------------------------------------------------------
// Kernel 1: row softmax + halved probs + entropy-like row scalar.
// One block per row, 256 threads, 3 elements per thread (768 = 3*256).
// ---------------------------------------------------------------------------
__global__ void softmax_rows_kernel(const float* __restrict__ z, int which) {
    __shared__ float red[256];
    const int row = blockIdx.x;
    const int t = threadIdx.x;
    const float* zr = z + row * DDIM;

    float* __restrict__ h = which ? g_h2 : g_h1;
    float* __restrict__ A = which ? g_B  : g_A;

    // row max
    float zv[3];
    float mx = -3.0e38f;
    #pragma unroll
    for (int k = 0; k < 3; k++) {
        zv[k] = zr[t + k * 256];
        mx = fmaxf(mx, zv[k]);
    }
    red[t] = mx;
    __syncthreads();
    for (int s = 128; s > 0; s >>= 1) {
        if (t < s) red[t] = fmaxf(red[t], red[t + s]);
        __syncthreads();
    }
    mx = red[0];
    __syncthreads();

    // exp + sum
    float e[3];
    float sum = 0.f;
    #pragma unroll
    for (int k = 0; k < 3; k++) {
        e[k] = __expf(zv[k] - mx);
        sum += e[k];
    }
    red[t] = sum;
    __syncthreads();
    for (int s = 128; s > 0; s >>= 1) {
        if (t < s) red[t] += red[t + s];
        __syncthreads();
    }
    const float inv = 1.0f / red[0];
    __syncthreads();

    // write 0.5*p, accumulate A_i = sum p*ln(p+eps)
    float a = 0.f;
    #pragma unroll
    for (int k = 0; k < 3; k++) {
        float p = e[k] * inv;
        a += p * __logf(p + c_eps);
        h[row * DDIM + t + k * 256] = 0.5f * p;
    }
    red[t] = a;
    __syncthreads();
    for (int s = 128; s > 0; s >>= 1) {
        if (t < s) red[t] += red[t + s];
        __syncthreads();
    }
    if (t == 0) A[row] = red[0];
}

// ---------------------------------------------------------------------------
// Kernel 2: cross term C[i][j] = sum_d m*ln(m+eps), m = h1[i,d] + h2[j,d]
// (h arrays already hold halved probabilities). 16x16 pair tile per block,
// d chunked by DC into padded smem. MUFU.LG2-bound by design.
// ---------------------------------------------------------------------------
__global__ __launch_bounds__(256) void pair_cross_kernel() {
    __shared__ float sA[TS * DCPAD];
    __shared__ float sB[TS * DCPAD];

    const int tx  = threadIdx.x;       // j within tile
    const int ty  = threadIdx.y;       // i within tile
    const int tid = ty * 16 + tx;
    const int i0  = blockIdx.y * TS;
    const int j0  = blockIdx.x * TS;

    float acc0 = 0.f, acc1 = 0.f, acc2 = 0.f, acc3 = 0.f;

    for (int c = 0; c < DDIM; c += DC) {
        // stage chunk: 16 rows x 192 floats per array = 768 float4 each;
        // 256 threads -> 3 float4 per thread per array
        #pragma unroll
        for (int f = tid; f < TS * (DC / 4); f += 256) {
            const int r  = f / (DC / 4);
            const int c4 = f % (DC / 4);
            float4 va = *(const float4*)&g_h1[(i0 + r) * DDIM + c + c4 * 4];
            float4 vb = *(const float4*)&g_h2[(j0 + r) * DDIM + c + c4 * 4];
            *(float4*)&sA[r * DCPAD + c4 * 4] = va;
            *(float4*)&sB[r * DCPAD + c4 * 4] = vb;
        }
        __syncthreads();

        const float* pa = &sA[ty * DCPAD];
        const float* pb = &sB[tx * DCPAD];

        #pragma unroll 8
        for (int d = 0; d < DC; d += 4) {
            float4 a = *(const float4*)&pa[d];   // broadcast: 1 LDS phase
            float4 b = *(const float4*)&pb[d];   // 2 conflict-free phases
            float m0 = a.x + b.x;
            float m1 = a.y + b.y;
            float m2 = a.z + b.z;
            float m3 = a.w + b.w;
            acc0 = fmaf(m0, __log2f(m0 + c_eps), acc0);
            acc1 = fmaf(m1, __log2f(m1 + c_eps), acc1);
            acc2 = fmaf(m2, __log2f(m2 + c_eps), acc2);
            acc3 = fmaf(m3, __log2f(m3 + c_eps), acc3);
        }
        __syncthreads();
    }

    // C_ij = ln2 * sum m*lg2(m+eps)
    const float C = 0.69314718055994530942f * ((acc0 + acc1) + (acc2 + acc3));

    // block reduction of tile sum + diagonal sum (reuse sA/sB as scratch)
    float* red  = sA;        // 256 floats
    float* redd = sB;        // 256 floats
    red[tid]  = C;
    redd[tid] = (i0 + ty == j0 + tx) ? C : 0.f;
    __syncthreads();
    for (int s = 128; s > 0; s >>= 1) {
        if (tid < s) {
            red[tid]  += red[tid + s];
            redd[tid] += redd[tid + s];
        }
        __syncthreads();
    }
    if (tid == 0) {
        const int b = blockIdx.y * gridDim.x + blockIdx.x;
        g_tileSum[b]  = red[0];
        g_tileDiag[b] = redd[0];
    }
}

// ---------------------------------------------------------------------------
// Kernel 3: final scalar combine (single block, deterministic).
// ---------------------------------------------------------------------------
__global__ void final_combine_kernel(float* __restrict__ out) {
    __shared__ float rA[512], rB[512], rS[512], rD[512];
    const int t = threadIdx.x;  // 512 threads

    rA[t] = g_A[t];
    rB[t] = g_B[t];
    rS[t] = g_tileSum[t]  + g_tileSum[t + 512];
    rD[t] = g_tileDiag[t] + g_tileDiag[t + 512];
    __syncthreads();
    for (int s = 256; s > 0; s >>= 1) {
        if (t < s) {
            rA[t] += rA[t + s];
            rB[t] += rB[t + s];
            rS[t] += rS[t + s];
            rD[t] += rD[t + s];
        }
        __syncthreads();
    }
    if (t == 0) {
        const double n      = (double)NROW;
        const double sumAB  = (double)rA[0] + (double)rB[0];
        const double S_all  = (double)rS[0];
        const double S_diag = (double)rD[0];
        // jsd[i][j] = 0.5*A_i + 0.5*B_j - C_ij
        const double sum_all_jsd  = 0.5 * n * sumAB - S_all;
        const double diag_sum_jsd = 0.5 * sumAB - S_diag;
        const double pos = diag_sum_jsd / n;
        const double neg = -(sum_all_jsd - diag_sum_jsd) / (n * n - n);
        out[0] = (float)(pos + 1.0 * neg);   // LAMBD = 1.0
    }
}

// ---------------------------------------------------------------------------
extern "C" void kernel_launch(void* const* d_in, const int* in_sizes, int n_in,
                              void* d_out, int out_size) {
    const float* z1 = (const float*)d_in[0];
    const float* z2 = (const float*)d_in[1];
    float* out = (float*)d_out;

    softmax_rows_kernel<<<NROW, 256>>>(z1, 0);
    softmax_rows_kernel<<<NROW, 256>>>(z2, 1);

    dim3 grid(NROW / TS, NROW / TS);   // 32 x 32 = 1024 tiles
    dim3 block(16, 16);
    pair_cross_kernel<<<grid, block>>>();

    final_combine_kernel<<<1, 512>>>(out);
}

// round 12
// speedup vs baseline: 1.0613x; 1.0613x over previous
#include <cuda_runtime.h>

#define NROW 512
#define DDIM 768
#define TS   16      // pair-tile side (i x j per block)
#define DC   192     // d-chunk per smem stage
#define DCPAD 196    // padded stride: 196 mod 32 == 4 -> LDS.128 quarter-warp tiles all 32 banks

__device__ float g_h1[NROW * DDIM];   // 0.5 * softmax(z1)
__device__ float g_h2[NROW * DDIM];   // 0.5 * softmax(z2)
__device__ float g_A[NROW];           // sum_d p1*ln(p1+eps) per row
__device__ float g_B[NROW];
__device__ float g_tileSum[1024];     // per 16x16 tile: sum C_ij
__device__ float g_tileDiag[1024];    // per tile: diagonal-only sum
__device__ unsigned g_counter;        // last-block election (reset by softmax kernel)

__constant__ float c_eps = 1e-8f;

__device__ __forceinline__ float warp_sum(float v) {
    #pragma unroll
    for (int o = 16; o > 0; o >>= 1) v += __shfl_xor_sync(0xffffffffu, v, o);
    return v;
}
__device__ __forceinline__ float warp_max(float v) {
    #pragma unroll
    for (int o = 16; o > 0; o >>= 1) v = fmaxf(v, __shfl_xor_sync(0xffffffffu, v, o));
    return v;
}

// ---------------------------------------------------------------------------
// Kernel 1: fused row softmax for BOTH inputs (1024 blocks).
// Writes 0.5*p and per-row A_i = sum p*ln(p+eps). Also resets g_counter.
// ---------------------------------------------------------------------------
__global__ __launch_bounds__(256) void softmax_fused_kernel(
    const float* __restrict__ z1, const float* __restrict__ z2) {
    __shared__ float ws[8];
    const int bid   = blockIdx.x;
    const int which = bid >> 9;
    const int row   = bid & 511;
    const int t     = threadIdx.x;
    const int warp  = t >> 5, lane = t & 31;

    const float* zr = (which ? z2 : z1) + row * DDIM;
    float* __restrict__ h = which ? g_h2 : g_h1;
    float* __restrict__ A = which ? g_B  : g_A;

    if (bid == 0 && t == 0) g_counter = 0;   // stream-ordered before pair kernel

    // row max
    float zv[3];
    float mx = -3.0e38f;
    #pragma unroll
    for (int k = 0; k < 3; k++) {
        zv[k] = zr[t + k * 256];
        mx = fmaxf(mx, zv[k]);
    }
    mx = warp_max(mx);
    if (lane == 0) ws[warp] = mx;
    __syncthreads();
    mx = ws[0];
    #pragma unroll
    for (int w = 1; w < 8; w++) mx = fmaxf(mx, ws[w]);
    __syncthreads();

    // exp + sum
    float e[3];
    float s = 0.f;
    #pragma unroll
    for (int k = 0; k < 3; k++) {
        e[k] = __expf(zv[k] - mx);
        s += e[k];
    }
    s = warp_sum(s);
    if (lane == 0) ws[warp] = s;
    __syncthreads();
    s = ((ws[0] + ws[1]) + (ws[2] + ws[3])) + ((ws[4] + ws[5]) + (ws[6] + ws[7]));
    const float inv = 1.0f / s;
    __syncthreads();

    // write 0.5*p, accumulate A_i
    float a = 0.f;
    #pragma unroll
    for (int k = 0; k < 3; k++) {
        float p = e[k] * inv;
        a += p * __logf(p + c_eps);
        h[row * DDIM + t + k * 256] = 0.5f * p;
    }
    a = warp_sum(a);
    if (lane == 0) ws[warp] = a;
    __syncthreads();
    if (t == 0)
        A[row] = ((ws[0] + ws[1]) + (ws[2] + ws[3])) + ((ws[4] + ws[5]) + (ws[6] + ws[7]));
}

// ---------------------------------------------------------------------------
// Kernel 2: cross term C[i][j] = sum_d m*ln(m+eps), m = h1[i,d] + h2[j,d],
// 16x16 pair tile per block, MUFU.LG2-bound mainloop. Last block performs
// the final 4-scalar combine and writes out[0] (no separate epilogue kernel).
// ---------------------------------------------------------------------------
__global__ __launch_bounds__(256) void pair_cross_kernel(float* __restrict__ out) {
    __shared__ float sA[TS * DCPAD];
    __shared__ float sB[TS * DCPAD];
    __shared__ float wred[16];
    __shared__ unsigned sLast;

    const int tx   = threadIdx.x;      // j within tile
    const int ty   = threadIdx.y;      // i within tile
    const int tid  = ty * 16 + tx;
    const int warp = tid >> 5, lane = tid & 31;
    const int i0   = blockIdx.y * TS;
    const int j0   = blockIdx.x * TS;

    float acc0 = 0.f, acc1 = 0.f, acc2 = 0.f, acc3 = 0.f;

    for (int c = 0; c < DDIM; c += DC) {
        // stage chunk: 16 rows x 48 float4 per array; 3 float4/thread/array
        #pragma unroll
        for (int f = tid; f < TS * (DC / 4); f += 256) {
            const int r  = f / (DC / 4);
            const int c4 = f % (DC / 4);
            *(float4*)&sA[r * DCPAD + c4 * 4] =
                *(const float4*)&g_h1[(i0 + r) * DDIM + c + c4 * 4];
            *(float4*)&sB[r * DCPAD + c4 * 4] =
                *(const float4*)&g_h2[(j0 + r) * DDIM + c + c4 * 4];
        }
        __syncthreads();

        const float* pa = &sA[ty * DCPAD];
        const float* pb = &sB[tx * DCPAD];

        #pragma unroll 8
        for (int d = 0; d < DC; d += 4) {
            float4 a = *(const float4*)&pa[d];   // broadcast within warp
            float4 b = *(const float4*)&pb[d];   // conflict-free phases
            float m0 = a.x + b.x;
            float m1 = a.y + b.y;
            float m2 = a.z + b.z;
            float m3 = a.w + b.w;
            acc0 = fmaf(m0, __log2f(m0 + c_eps), acc0);
            acc1 = fmaf(m1, __log2f(m1 + c_eps), acc1);
            acc2 = fmaf(m2, __log2f(m2 + c_eps), acc2);
            acc3 = fmaf(m3, __log2f(m3 + c_eps), acc3);
        }
        __syncthreads();
    }

    // C_ij = ln2 * sum m*lg2(m+eps); shuffle-based block reduction
    const float C  = 0.69314718055994530942f * ((acc0 + acc1) + (acc2 + acc3));
    const float Cd = (i0 + ty == j0 + tx) ? C : 0.f;
    float ws_ = warp_sum(C);
    float wd_ = warp_sum(Cd);
    if (lane == 0) { wred[warp] = ws_; wred[8 + warp] = wd_; }
    __syncthreads();

    if (tid == 0) {
        float ts = 0.f, td = 0.f;
        #pragma unroll
        for (int w = 0; w < 8; w++) { ts += wred[w]; td += wred[8 + w]; }
        const int b = blockIdx.y * gridDim.x + blockIdx.x;
        g_tileSum[b]  = ts;
        g_tileDiag[b] = td;
        __threadfence();
        unsigned old = atomicAdd(&g_counter, 1u);
        sLast = (old == 1023u) ? 1u : 0u;
    }
    __syncthreads();
    if (!sLast) return;

    // ---- last block: final combine (deterministic read order, L2 reads) ----
    float fa = __ldcg(&g_A[tid]) + __ldcg(&g_A[tid + 256]);
    float fb = __ldcg(&g_B[tid]) + __ldcg(&g_B[tid + 256]);
    float fs = (__ldcg(&g_tileSum[tid])       + __ldcg(&g_tileSum[tid + 256])) +
               (__ldcg(&g_tileSum[tid + 512]) + __ldcg(&g_tileSum[tid + 768]));
    float fd = (__ldcg(&g_tileDiag[tid])       + __ldcg(&g_tileDiag[tid + 256])) +
               (__ldcg(&g_tileDiag[tid + 512]) + __ldcg(&g_tileDiag[tid + 768]));
    fa = warp_sum(fa);
    fb = warp_sum(fb);
    fs = warp_sum(fs);
    fd = warp_sum(fd);
    __syncthreads();   // before wred/sA scratch reuse
    if (lane == 0) {
        wred[warp]     = fa;
        wred[8 + warp] = fb;
        sA[warp]       = fs;
        sA[8 + warp]   = fd;
    }
    __syncthreads();
    if (tid == 0) {
        double SA = 0.0, SB = 0.0, SS = 0.0, SD = 0.0;
        #pragma unroll
        for (int w = 0; w < 8; w++) {
            SA += wred[w]; SB += wred[8 + w];
            SS += sA[w];   SD += sA[8 + w];
        }
        const double n      = (double)NROW;
        const double sumAB  = SA + SB;
        // jsd[i][j] = 0.5*A_i + 0.5*B_j - C_ij
        const double sum_all_jsd  = 0.5 * n * sumAB - SS;
        const double diag_sum_jsd = 0.5 * sumAB - SD;
        const double pos = diag_sum_jsd / n;
        const double neg = -(sum_all_jsd - diag_sum_jsd) / (n * n - n);
        out[0] = (float)(pos + neg);   // LAMBD = 1.0
    }
}

// ---------------------------------------------------------------------------
extern "C" void kernel_launch(void* const* d_in, const int* in_sizes, int n_in,
                              void* d_out, int out_size) {
    const float* z1 = (const float*)d_in[0];
    const float* z2 = (const float*)d_in[1];
    float* out = (float*)d_out;

    softmax_fused_kernel<<<2 * NROW, 256>>>(z1, z2);

    dim3 grid(NROW / TS, NROW / TS);   // 32 x 32 = 1024 tiles
    dim3 block(16, 16);
    pair_cross_kernel<<<grid, block>>>(out);
}